// round 12
// baseline (speedup 1.0000x reference)
#include <cuda_runtime.h>
#include <cuda_fp16.h>

#define NN 50000
#define NE 800000
#define NEP (NE + 4 * NN)   // CSR rows padded to multiples of 4
#define HID 64
#define NG 64
#define GCN_BLOCKS 1184   // up to 8 blocks/SM (256 thr, ~20.5KB smem)

// ---------------- persistent device scratch (allocation-free) ----------------
struct ZBlock {
    int   deg[NN];
    int   cnt[NG];
    int   ticket;
    int   pad[3];
    float pool[NG * HID];
};
__device__ ZBlock g_z;

__device__ __align__(16) __half2 g_xs1[NN * HID / 2];  // x*dinv after layer1 (fp16)
__device__ __align__(16) __half2 g_xs2[NN * HID / 2];  // x*dinv after layer2 (fp16)
__device__ __align__(16) float  g_e4s[NN * 4];         // emb[node]*dinv
__device__ float g_dinv[NN];
__device__ int   g_rowbeg[NN];
__device__ int   g_rank[NE];
__device__ __align__(16) int g_col[NEP];

// ---------------- packed f32x2 helpers (Blackwell FFMA2, PTX-only) ----------------
__device__ __forceinline__ unsigned long long pack2(float a, float b) {
    unsigned long long r;
    asm("mov.b64 %0, {%1, %2};" : "=l"(r)
        : "r"(__float_as_uint(a)), "r"(__float_as_uint(b)));
    return r;
}
__device__ __forceinline__ void unpack2(unsigned long long v, float& a, float& b) {
    unsigned int lo, hi;
    asm("mov.b64 {%0, %1}, %2;" : "=r"(lo), "=r"(hi) : "l"(v));
    a = __uint_as_float(lo);
    b = __uint_as_float(hi);
}
__device__ __forceinline__ void ffma2(unsigned long long& d, unsigned long long a,
                                      unsigned long long b) {
    asm("fma.rn.f32x2 %0, %1, %2, %3;" : "=l"(d) : "l"(a), "l"(b), "l"(d));
}

// ---------------- setup kernels ----------------
__global__ __launch_bounds__(256) void k_deg(const int* __restrict__ dst) {
    int e = blockIdx.x * blockDim.x + threadIdx.x;
    if (e < NE) g_rank[e] = atomicAdd(&g_z.deg[dst[e]], 1);
}

// single-pass scan over 4-padded row sizes + global ticket for block base.
__global__ __launch_bounds__(256) void k_scan(const int* __restrict__ node,
                                              const float* __restrict__ emb) {
    __shared__ int sh[256];
    __shared__ int base;
    int t = threadIdx.x;
    int i = blockIdx.x * 256 + t;
    int d = (i < NN) ? g_z.deg[i] : 0;
    int p = (d + 3) & ~3;                // padded row size (keeps rows 16B-aligned)
    sh[t] = p;
    __syncthreads();
    for (int o = 1; o < 256; o <<= 1) {
        int v = (t >= o) ? sh[t - o] : 0;
        __syncthreads();
        sh[t] += v;
        __syncthreads();
    }
    if (t == 255) base = atomicAdd(&g_z.ticket, sh[255]);
    __syncthreads();
    if (i < NN) {
        g_rowbeg[i] = base + sh[t] - p;
        float di = rsqrtf((float)(d + 1));
        g_dinv[i] = di;
        float4 e = ((const float4*)emb)[node[i]];
        ((float4*)g_e4s)[i] = make_float4(e.x * di, e.y * di, e.z * di, e.w * di);
    }
}

// pure scatter (no atomics; rank captured in k_deg)
__global__ __launch_bounds__(256) void k_fill(const int* __restrict__ src,
                                              const int* __restrict__ dst) {
    int e = blockIdx.x * blockDim.x + threadIdx.x;
    if (e < NE) {
        int d = __ldg(&dst[e]);
        g_col[g_rowbeg[d] + g_rank[e]] = __ldg(&src[e]);
    }
}

// ---------------- layer 1 fused: 8 lanes per node ----------------
__global__ __launch_bounds__(256) void k_layer1(const float* __restrict__ W1,
                                                const float* __restrict__ b1,
                                                const float* __restrict__ lng,
                                                const float* __restrict__ lnb) {
    __shared__ float sW[4 * HID];   // [k][j]
    int t = threadIdx.x;
    sW[t] = W1[t];
    __syncthreads();
    int n = (blockIdx.x * 256 + t) >> 3;
    int sub = t & 7;
    if (n >= NN) return;
    const float4* e4 = (const float4*)g_e4s;
    int beg = g_rowbeg[n];
    int end = beg + g_z.deg[n];
    float ax = 0.f, ay = 0.f, az = 0.f, aw = 0.f;
    int e = beg + sub;
    for (; e + 8 < end; e += 16) {   // two in flight per lane
        int c0 = __ldg(&g_col[e]);
        int c1 = __ldg(&g_col[e + 8]);
        float4 v0 = __ldg(&e4[c0]);
        float4 v1 = __ldg(&e4[c1]);
        ax += v0.x + v1.x;
        ay += v0.y + v1.y;
        az += v0.z + v1.z;
        aw += v0.w + v1.w;
    }
    if (e < end) {
        float4 v = __ldg(&e4[__ldg(&g_col[e])]);
        ax += v.x; ay += v.y; az += v.z; aw += v.w;
    }
#pragma unroll
    for (int o = 4; o; o >>= 1) {
        ax += __shfl_xor_sync(0xffffffffu, ax, o);
        ay += __shfl_xor_sync(0xffffffffu, ay, o);
        az += __shfl_xor_sync(0xffffffffu, az, o);
        aw += __shfl_xor_sync(0xffffffffu, aw, o);
    }
    float4 self = __ldg(&e4[n]);
    float di = g_dinv[n];
    ax = (ax + self.x) * di;
    ay = (ay + self.y) * di;
    az = (az + self.z) * di;
    aw = (aw + self.w) * di;
    int jb = sub * 8;
    float v[8];
    float mu = 0.f;
#pragma unroll
    for (int u = 0; u < 8; u++) {
        int j = jb + u;
        float r = fmaf(ax, sW[j], fmaf(ay, sW[64 + j],
                  fmaf(az, sW[128 + j], fmaf(aw, sW[192 + j], __ldg(&b1[j])))));
        r = fmaxf(r, 0.f);
        v[u] = r;
        mu += r;
    }
#pragma unroll
    for (int o = 4; o; o >>= 1) mu += __shfl_xor_sync(0xffffffffu, mu, o);
    mu *= (1.f / 64.f);
    float q = 0.f;
#pragma unroll
    for (int u = 0; u < 8; u++) {
        float d = v[u] - mu;
        v[u] = d;
        q = fmaf(d, d, q);
    }
#pragma unroll
    for (int o = 4; o; o >>= 1) q += __shfl_xor_sync(0xffffffffu, q, o);
    float rs = rsqrtf(q * (1.f / 64.f) + 1e-5f);
    __half2 hv[4];
#pragma unroll
    for (int u = 0; u < 4; u++) {
        int j = jb + 2 * u;
        float ox = fmaf(v[2 * u] * rs, __ldg(&lng[j]), __ldg(&lnb[j])) * di;
        float oy = fmaf(v[2 * u + 1] * rs, __ldg(&lng[j + 1]), __ldg(&lnb[j + 1])) * di;
        hv[u] = __floats2half2_rn(ox, oy);
    }
    ((float2*)g_xs1)[(size_t)n * 16 + sub * 2 + 0] = *(float2*)&hv[0];
    ((float2*)g_xs1)[(size_t)n * 16 + sub * 2 + 1] = *(float2*)&hv[2];
}

// ---------------- fused GCN layer, PERSISTENT blocks, FFMA2 projection ----------------
// Index loads: int4 (rows 4-aligned). Gather accumulation: HADD2 tree.
// y staged pre-duplicated: y2[k] = (y_k, y_k) packed 64-bit.
template <bool LN, bool POOL>
__global__ __launch_bounds__(256) void k_gcn(const __half2* __restrict__ xs,
                                             const float* __restrict__ W,
                                             const float* __restrict__ bias,
                                             const float* __restrict__ lng,
                                             const float* __restrict__ lnb,
                                             const int* __restrict__ batch,
                                             __half2* __restrict__ xs_out) {
    __shared__ float4 sWq[32 * 32];                              // 16 KB
    __shared__ __align__(16) unsigned long long sy2[8 * HID];    // 4 KB, duplicated y
    int t = threadIdx.x;
    for (int i = t; i < HID * HID; i += 256) {
        int k = i >> 6, j = i & 63;
        float w = W[i];
        float* cell = (float*)&sWq[(k >> 1) * 32 + (j & 31)];
        cell[(k & 1) * 2 + (j >> 5)] = w;
    }
    __syncthreads();
    int lane = t & 31;
    int wid = t >> 5;
    unsigned long long* y2 = sy2 + wid * HID;
    const ulonglong2* wq = (const ulonglong2*)sWq;
    unsigned long long bpair = pack2(__ldg(&bias[lane]), __ldg(&bias[lane + 32]));
    int gw = blockIdx.x * 8 + wid;
    int tw = gridDim.x * 8;
    for (int n = gw; n < NN; n += tw) {
        float2 sf = __half22float2(__ldg(&xs[(size_t)n * 32 + lane]));  // self term
        float accx = sf.x, accy = sf.y;
        int beg = g_rowbeg[n];
        int end = beg + g_z.deg[n];
        int e = beg;
        while (end - e >= 16) {
            int4 qa = *(const int4*)(g_col + e);
            int4 qb = *(const int4*)(g_col + e + 4);
            int4 qc = *(const int4*)(g_col + e + 8);
            int4 qd = *(const int4*)(g_col + e + 12);
            __half2 v0 = __ldg(&xs[(size_t)qa.x * 32 + lane]);
            __half2 v1 = __ldg(&xs[(size_t)qa.y * 32 + lane]);
            __half2 v2 = __ldg(&xs[(size_t)qa.z * 32 + lane]);
            __half2 v3 = __ldg(&xs[(size_t)qa.w * 32 + lane]);
            __half2 v4 = __ldg(&xs[(size_t)qb.x * 32 + lane]);
            __half2 v5 = __ldg(&xs[(size_t)qb.y * 32 + lane]);
            __half2 v6 = __ldg(&xs[(size_t)qb.z * 32 + lane]);
            __half2 v7 = __ldg(&xs[(size_t)qb.w * 32 + lane]);
            __half2 v8 = __ldg(&xs[(size_t)qc.x * 32 + lane]);
            __half2 v9 = __ldg(&xs[(size_t)qc.y * 32 + lane]);
            __half2 va = __ldg(&xs[(size_t)qc.z * 32 + lane]);
            __half2 vb = __ldg(&xs[(size_t)qc.w * 32 + lane]);
            __half2 vc = __ldg(&xs[(size_t)qd.x * 32 + lane]);
            __half2 vd = __ldg(&xs[(size_t)qd.y * 32 + lane]);
            __half2 ve = __ldg(&xs[(size_t)qd.z * 32 + lane]);
            __half2 vf = __ldg(&xs[(size_t)qd.w * 32 + lane]);
            __half2 t0 = __hadd2(v0, v1), t1 = __hadd2(v2, v3);
            __half2 t2 = __hadd2(v4, v5), t3 = __hadd2(v6, v7);
            __half2 t4 = __hadd2(v8, v9), t5 = __hadd2(va, vb);
            __half2 t6 = __hadd2(vc, vd), t7 = __hadd2(ve, vf);
            __half2 u0 = __hadd2(t0, t1), u1 = __hadd2(t2, t3);
            __half2 u2 = __hadd2(t4, t5), u3 = __hadd2(t6, t7);
            __half2 r = __hadd2(__hadd2(u0, u1), __hadd2(u2, u3));
            float2 f = __half22float2(r);
            accx += f.x;
            accy += f.y;
            e += 16;
        }
        if (end - e >= 8) {
            int4 qa = *(const int4*)(g_col + e);
            int4 qb = *(const int4*)(g_col + e + 4);
            __half2 v0 = __ldg(&xs[(size_t)qa.x * 32 + lane]);
            __half2 v1 = __ldg(&xs[(size_t)qa.y * 32 + lane]);
            __half2 v2 = __ldg(&xs[(size_t)qa.z * 32 + lane]);
            __half2 v3 = __ldg(&xs[(size_t)qa.w * 32 + lane]);
            __half2 v4 = __ldg(&xs[(size_t)qb.x * 32 + lane]);
            __half2 v5 = __ldg(&xs[(size_t)qb.y * 32 + lane]);
            __half2 v6 = __ldg(&xs[(size_t)qb.z * 32 + lane]);
            __half2 v7 = __ldg(&xs[(size_t)qb.w * 32 + lane]);
            __half2 t0 = __hadd2(v0, v1), t1 = __hadd2(v2, v3);
            __half2 t2 = __hadd2(v4, v5), t3 = __hadd2(v6, v7);
            __half2 r = __hadd2(__hadd2(t0, t1), __hadd2(t2, t3));
            float2 f = __half22float2(r);
            accx += f.x;
            accy += f.y;
            e += 8;
        }
        for (; e < end; e++) {
            int s = __ldg(&g_col[e]);
            float2 v = __half22float2(__ldg(&xs[(size_t)s * 32 + lane]));
            accx += v.x;
            accy += v.y;
        }
        float di = g_dinv[n];
        float yx = accx * di, yy = accy * di;
        y2[2 * lane] = pack2(yx, yx);
        y2[2 * lane + 1] = pack2(yy, yy);
        __syncwarp();
        unsigned long long accA = bpair;     // even-k partial (+bias)
        unsigned long long accB = 0;         // odd-k partial
#pragma unroll
        for (int k4 = 0; k4 < 16; k4++) {
            ulonglong2 y01 = *(const ulonglong2*)(y2 + 4 * k4);       // broadcast
            ulonglong2 y23 = *(const ulonglong2*)(y2 + 4 * k4 + 2);   // broadcast
            ulonglong2 q0 = wq[(2 * k4 + 0) * 32 + lane];
            ulonglong2 q1 = wq[(2 * k4 + 1) * 32 + lane];
            ffma2(accA, y01.x, q0.x);
            ffma2(accB, y01.y, q0.y);
            ffma2(accA, y23.x, q1.x);
            ffma2(accB, y23.y, q1.y);
        }
        __syncwarp();
        float a0, a1, c0, c1;
        unpack2(accA, a0, a1);
        unpack2(accB, c0, c1);
        float vx = fmaxf(a0 + c0, 0.f);   // output feature f0 = lane
        float vy = fmaxf(a1 + c1, 0.f);   // output feature f1 = lane + 32
        if (LN) {
            float s = vx + vy;
#pragma unroll
            for (int o = 16; o; o >>= 1) s += __shfl_xor_sync(0xffffffffu, s, o);
            float mu = s * (1.f / 64.f);
            float dx = vx - mu, dy = vy - mu;
            float q = dx * dx + dy * dy;
#pragma unroll
            for (int o = 16; o; o >>= 1) q += __shfl_xor_sync(0xffffffffu, q, o);
            float r = rsqrtf(q * (1.f / 64.f) + 1e-5f);
            vx = fmaf(dx * r, __ldg(&lng[lane]), __ldg(&lnb[lane]));
            vy = fmaf(dy * r, __ldg(&lng[lane + 32]), __ldg(&lnb[lane + 32]));
        }
        if (POOL) {
            int g = __ldg(&batch[n]);
            atomicAdd(&g_z.pool[g * HID + lane], vx);
            atomicAdd(&g_z.pool[g * HID + lane + 32], vy);
            if (lane == 0) atomicAdd(&g_z.cnt[g], 1);
        } else {
            __half* ho = (__half*)xs_out;
            ho[(size_t)n * 64 + lane] = __float2half(vx * di);
            ho[(size_t)n * 64 + lane + 32] = __float2half(vy * di);
        }
    }
}

// ---------------- final MLP: one block per graph ----------------
__global__ __launch_bounds__(64) void k_mlp(const float* __restrict__ pW1,
                                            const float* __restrict__ pb1,
                                            const float* __restrict__ pW2,
                                            const float* __restrict__ pb2,
                                            float* __restrict__ out) {
    __shared__ float sp[HID];
    __shared__ float sh[HID];
    int g = blockIdx.x;
    int j = threadIdx.x;
    float c = (float)max(g_z.cnt[g], 1);
    sp[j] = g_z.pool[g * HID + j] / c;
    __syncthreads();
    float a = __ldg(&pb1[j]);
#pragma unroll 8
    for (int k = 0; k < HID; k++) a = fmaf(sp[k], __ldg(&pW1[k * HID + j]), a);
    sh[j] = a;
    __syncthreads();
    float b = __ldg(&pb2[j]);
#pragma unroll 8
    for (int k = 0; k < HID; k++) b = fmaf(sh[k], __ldg(&pW2[k * HID + j]), b);
    out[g * HID + j] = b;
}

// ---------------- launcher ----------------
extern "C" void kernel_launch(void* const* d_in, const int* in_sizes, int n_in,
                              void* d_out, int out_size) {
    const int* node = (const int*)d_in[0];
    const int* src = (const int*)d_in[1];
    const int* dst = (const int*)d_in[2];
    const int* batch = (const int*)d_in[3];
    const float* emb = (const float*)d_in[4];
    const float* W1 = (const float*)d_in[5];
    const float* b1 = (const float*)d_in[6];
    const float* W2 = (const float*)d_in[7];
    const float* b2 = (const float*)d_in[8];
    const float* W3 = (const float*)d_in[9];
    const float* b3 = (const float*)d_in[10];
    const float* ln1g = (const float*)d_in[11];
    const float* ln1b = (const float*)d_in[12];
    const float* ln2g = (const float*)d_in[13];
    const float* ln2b = (const float*)d_in[14];
    const float* pW1 = (const float*)d_in[15];
    const float* pb1 = (const float*)d_in[16];
    const float* pW2 = (const float*)d_in[17];
    const float* pb2 = (const float*)d_in[18];
    float* out = (float*)d_out;

    void* zptr = nullptr;
    cudaGetSymbolAddress(&zptr, g_z);
    void* xs1p = nullptr;
    cudaGetSymbolAddress(&xs1p, g_xs1);
    void* xs2p = nullptr;
    cudaGetSymbolAddress(&xs2p, g_xs2);
    __half2* xs1 = (__half2*)xs1p;
    __half2* xs2 = (__half2*)xs2p;

    cudaMemsetAsync(zptr, 0, sizeof(ZBlock));

    const int TB = 256;
    k_deg<<<(NE + TB - 1) / TB, TB>>>(dst);
    k_scan<<<(NN + TB - 1) / TB, TB>>>(node, emb);
    k_fill<<<(NE + TB - 1) / TB, TB>>>(src, dst);

    dim3 g8((NN * 8 + TB - 1) / TB);

    // layer 1 (8 lanes/node) -> xs1
    k_layer1<<<g8, TB>>>(W1, b1, ln1g, ln1b);
    // layer 2 fused gather+project (+LN) -> xs2, persistent blocks
    k_gcn<true, false><<<GCN_BLOCKS, TB>>>(xs1, W2, b2, ln2g, ln2b, nullptr, xs2);
    // layer 3 fused gather+project (+pool), persistent blocks
    k_gcn<false, true><<<GCN_BLOCKS, TB>>>(xs2, W3, b3, nullptr, nullptr, batch, nullptr);
    // MLP head: one block per graph
    k_mlp<<<NG, 64>>>(pW1, pb1, pW2, pb2, out);
}

// round 13
// speedup vs baseline: 1.1457x; 1.1457x over previous
#include <cuda_runtime.h>
#include <cuda_fp16.h>

#define NN 50000
#define NE 800000
#define HID 64
#define NG 64
#define GCN_BLOCKS 1184   // up to 8 blocks/SM (256 thr, ~18.25KB smem)

// ---------------- persistent device scratch (allocation-free) ----------------
struct ZBlock {
    int   deg[NN];
    int   cnt[NG];
    int   ticket;
    int   pad[3];
    float pool[NG * HID];
};
__device__ ZBlock g_z;

__device__ __align__(16) __half2 g_xs1[NN * HID / 2];  // x*dinv after layer1 (fp16)
__device__ __align__(16) __half2 g_xs2[NN * HID / 2];  // x*dinv after layer2 (fp16)
__device__ __align__(16) float  g_e4s[NN * 4];         // emb[node]*dinv
__device__ float g_dinv[NN];
__device__ int   g_rowbeg[NN];
__device__ int   g_rank[NE];
__device__ int   g_col[NE];

// ---------------- packed f32x2 helpers (Blackwell FFMA2, PTX-only) ----------------
__device__ __forceinline__ unsigned long long pack2(float a, float b) {
    unsigned long long r;
    asm("mov.b64 %0, {%1, %2};" : "=l"(r)
        : "r"(__float_as_uint(a)), "r"(__float_as_uint(b)));
    return r;
}
__device__ __forceinline__ void unpack2(unsigned long long v, float& a, float& b) {
    unsigned int lo, hi;
    asm("mov.b64 {%0, %1}, %2;" : "=r"(lo), "=r"(hi) : "l"(v));
    a = __uint_as_float(lo);
    b = __uint_as_float(hi);
}
__device__ __forceinline__ void ffma2(unsigned long long& d, unsigned long long a,
                                      unsigned long long b) {
    asm("fma.rn.f32x2 %0, %1, %2, %3;" : "=l"(d) : "l"(a), "l"(b), "l"(d));
}

// ---------------- setup kernels ----------------
__global__ __launch_bounds__(256) void k_deg(const int* __restrict__ dst) {
    int e = blockIdx.x * blockDim.x + threadIdx.x;
    if (e < NE) g_rank[e] = atomicAdd(&g_z.deg[dst[e]], 1);
}

// single-pass scan: per-block inclusive scan + global ticket for block base.
__global__ __launch_bounds__(256) void k_scan(const int* __restrict__ node,
                                              const float* __restrict__ emb) {
    __shared__ int sh[256];
    __shared__ int base;
    int t = threadIdx.x;
    int i = blockIdx.x * 256 + t;
    int d = (i < NN) ? g_z.deg[i] : 0;
    sh[t] = d;
    __syncthreads();
    for (int o = 1; o < 256; o <<= 1) {
        int v = (t >= o) ? sh[t - o] : 0;
        __syncthreads();
        sh[t] += v;
        __syncthreads();
    }
    if (t == 255) base = atomicAdd(&g_z.ticket, sh[255]);
    __syncthreads();
    if (i < NN) {
        g_rowbeg[i] = base + sh[t] - d;
        float di = rsqrtf((float)(d + 1));
        g_dinv[i] = di;
        float4 e = ((const float4*)emb)[node[i]];
        ((float4*)g_e4s)[i] = make_float4(e.x * di, e.y * di, e.z * di, e.w * di);
    }
}

// pure scatter (no atomics; rank captured in k_deg)
__global__ __launch_bounds__(256) void k_fill(const int* __restrict__ src,
                                              const int* __restrict__ dst) {
    int e = blockIdx.x * blockDim.x + threadIdx.x;
    if (e < NE) {
        int d = __ldg(&dst[e]);
        g_col[g_rowbeg[d] + g_rank[e]] = __ldg(&src[e]);
    }
}

// ---------------- layer 1 fused: 16 lanes per node (one gather latency round) ----------------
// gather 4-dim e4s (1 edge/lane typical), 16-lane reduce, each lane produces
// 4 of 64 outputs, group LayerNorm, write xs1 = x*dinv (fp16).
__global__ __launch_bounds__(256) void k_layer1(const float* __restrict__ W1,
                                                const float* __restrict__ b1,
                                                const float* __restrict__ lng,
                                                const float* __restrict__ lnb) {
    __shared__ float sW[4 * HID];   // [k][j]
    int t = threadIdx.x;
    sW[t] = W1[t];
    __syncthreads();
    int n = (blockIdx.x * 256 + t) >> 4;
    int sub = t & 15;
    if (n >= NN) return;
    const float4* e4 = (const float4*)g_e4s;
    int beg = g_rowbeg[n];
    int end = beg + g_z.deg[n];
    float ax = 0.f, ay = 0.f, az = 0.f, aw = 0.f;
    for (int e = beg + sub; e < end; e += 16) {   // one round covers mean degree
        float4 v = __ldg(&e4[__ldg(&g_col[e])]);
        ax += v.x; ay += v.y; az += v.z; aw += v.w;
    }
#pragma unroll
    for (int o = 8; o; o >>= 1) {   // reduce within 16-lane group
        ax += __shfl_xor_sync(0xffffffffu, ax, o);
        ay += __shfl_xor_sync(0xffffffffu, ay, o);
        az += __shfl_xor_sync(0xffffffffu, az, o);
        aw += __shfl_xor_sync(0xffffffffu, aw, o);
    }
    float4 self = __ldg(&e4[n]);
    float di = g_dinv[n];
    // out = dinv[n]*(Sum_src e4s[src] + e4s[n])
    ax = (ax + self.x) * di;
    ay = (ay + self.y) * di;
    az = (az + self.z) * di;
    aw = (aw + self.w) * di;
    // each lane: outputs j = sub*4 .. sub*4+3
    int jb = sub * 4;
    float4 w0 = *(const float4*)(sW + jb);
    float4 w1 = *(const float4*)(sW + 64 + jb);
    float4 w2 = *(const float4*)(sW + 128 + jb);
    float4 w3 = *(const float4*)(sW + 192 + jb);
    float4 bb = *(const float4*)(b1 + jb);
    float v[4];
    v[0] = fmaxf(fmaf(ax, w0.x, fmaf(ay, w1.x, fmaf(az, w2.x, fmaf(aw, w3.x, bb.x)))), 0.f);
    v[1] = fmaxf(fmaf(ax, w0.y, fmaf(ay, w1.y, fmaf(az, w2.y, fmaf(aw, w3.y, bb.y)))), 0.f);
    v[2] = fmaxf(fmaf(ax, w0.z, fmaf(ay, w1.z, fmaf(az, w2.z, fmaf(aw, w3.z, bb.z)))), 0.f);
    v[3] = fmaxf(fmaf(ax, w0.w, fmaf(ay, w1.w, fmaf(az, w2.w, fmaf(aw, w3.w, bb.w)))), 0.f);
    float mu = (v[0] + v[1]) + (v[2] + v[3]);
#pragma unroll
    for (int o = 8; o; o >>= 1) mu += __shfl_xor_sync(0xffffffffu, mu, o);
    mu *= (1.f / 64.f);
    float q = 0.f;
#pragma unroll
    for (int u = 0; u < 4; u++) {
        float d = v[u] - mu;
        v[u] = d;
        q = fmaf(d, d, q);
    }
#pragma unroll
    for (int o = 8; o; o >>= 1) q += __shfl_xor_sync(0xffffffffu, q, o);
    float rs = rsqrtf(q * (1.f / 64.f) + 1e-5f);
    float4 gg = *(const float4*)(lng + jb);
    float4 be = *(const float4*)(lnb + jb);
    __half2 hv[2];
    hv[0] = __floats2half2_rn(fmaf(v[0] * rs, gg.x, be.x) * di,
                              fmaf(v[1] * rs, gg.y, be.y) * di);
    hv[1] = __floats2half2_rn(fmaf(v[2] * rs, gg.z, be.z) * di,
                              fmaf(v[3] * rs, gg.w, be.w) * di);
    ((float2*)g_xs1)[(size_t)n * 16 + sub] = *(float2*)&hv[0];
}

// ---------------- fused GCN layer, PERSISTENT blocks, FFMA2 projection (R11 exact) ----------------
template <bool LN, bool POOL>
__global__ __launch_bounds__(256) void k_gcn(const __half2* __restrict__ xs,
                                             const float* __restrict__ W,
                                             const float* __restrict__ bias,
                                             const float* __restrict__ lng,
                                             const float* __restrict__ lnb,
                                             const int* __restrict__ batch,
                                             __half2* __restrict__ xs_out) {
    __shared__ float4 sWq[32 * 32];      // 16 KB
    __shared__ float sy[8 * HID];        // per-warp aggregated vector
    int t = threadIdx.x;
    for (int i = t; i < HID * HID; i += 256) {
        int k = i >> 6, j = i & 63;
        float w = W[i];
        float* cell = (float*)&sWq[(k >> 1) * 32 + (j & 31)];
        cell[(k & 1) * 2 + (j >> 5)] = w;
    }
    __syncthreads();
    int lane = t & 31;
    int wid = t >> 5;
    float* y = sy + wid * HID;
    const ulonglong2* wq = (const ulonglong2*)sWq;
    unsigned long long bpair = pack2(__ldg(&bias[lane]), __ldg(&bias[lane + 32]));
    int gw = blockIdx.x * 8 + wid;
    int tw = gridDim.x * 8;
    for (int n = gw; n < NN; n += tw) {
        float2 sf = __half22float2(__ldg(&xs[(size_t)n * 32 + lane]));  // self term
        float accx = sf.x, accy = sf.y;
        int beg = g_rowbeg[n];
        int end = beg + g_z.deg[n];
        int e = beg;
        while (end - e >= 16) {      // one latency round covers mean degree
            int s[16];
#pragma unroll
            for (int u = 0; u < 16; u++) s[u] = __ldg(&g_col[e + u]);
            float2 v[16];
#pragma unroll
            for (int u = 0; u < 16; u++)
                v[u] = __half22float2(__ldg(&xs[(size_t)s[u] * 32 + lane]));
#pragma unroll
            for (int u = 0; u < 16; u++) {
                accx += v[u].x;
                accy += v[u].y;
            }
            e += 16;
        }
        if (end - e >= 8) {
            int s[8];
#pragma unroll
            for (int u = 0; u < 8; u++) s[u] = __ldg(&g_col[e + u]);
            float2 v[8];
#pragma unroll
            for (int u = 0; u < 8; u++)
                v[u] = __half22float2(__ldg(&xs[(size_t)s[u] * 32 + lane]));
#pragma unroll
            for (int u = 0; u < 8; u++) {
                accx += v[u].x;
                accy += v[u].y;
            }
            e += 8;
        }
        for (; e < end; e++) {
            int s = __ldg(&g_col[e]);
            float2 v = __half22float2(__ldg(&xs[(size_t)s * 32 + lane]));
            accx += v.x;
            accy += v.y;
        }
        float di = g_dinv[n];
        y[2 * lane] = accx * di;
        y[2 * lane + 1] = accy * di;
        __syncwarp();
        unsigned long long accA = bpair;     // even-k partial (+bias)
        unsigned long long accB = 0;         // odd-k partial
#pragma unroll
        for (int k4 = 0; k4 < 16; k4++) {
            float4 yv = *(const float4*)(y + 4 * k4);   // broadcast LDS.128
            ulonglong2 q0 = wq[(2 * k4 + 0) * 32 + lane];   // (k0 pair, k1 pair)
            ulonglong2 q1 = wq[(2 * k4 + 1) * 32 + lane];   // (k2 pair, k3 pair)
            ffma2(accA, pack2(yv.x, yv.x), q0.x);
            ffma2(accB, pack2(yv.y, yv.y), q0.y);
            ffma2(accA, pack2(yv.z, yv.z), q1.x);
            ffma2(accB, pack2(yv.w, yv.w), q1.y);
        }
        __syncwarp();
        float a0, a1, c0, c1;
        unpack2(accA, a0, a1);
        unpack2(accB, c0, c1);
        float vx = fmaxf(a0 + c0, 0.f);   // output feature f0 = lane
        float vy = fmaxf(a1 + c1, 0.f);   // output feature f1 = lane + 32
        if (LN) {
            float s = vx + vy;
#pragma unroll
            for (int o = 16; o; o >>= 1) s += __shfl_xor_sync(0xffffffffu, s, o);
            float mu = s * (1.f / 64.f);
            float dx = vx - mu, dy = vy - mu;
            float q = dx * dx + dy * dy;
#pragma unroll
            for (int o = 16; o; o >>= 1) q += __shfl_xor_sync(0xffffffffu, q, o);
            float r = rsqrtf(q * (1.f / 64.f) + 1e-5f);
            vx = fmaf(dx * r, __ldg(&lng[lane]), __ldg(&lnb[lane]));
            vy = fmaf(dy * r, __ldg(&lng[lane + 32]), __ldg(&lnb[lane + 32]));
        }
        if (POOL) {
            int g = __ldg(&batch[n]);
            atomicAdd(&g_z.pool[g * HID + lane], vx);
            atomicAdd(&g_z.pool[g * HID + lane + 32], vy);
            if (lane == 0) atomicAdd(&g_z.cnt[g], 1);
        } else {
            __half* ho = (__half*)xs_out;
            ho[(size_t)n * 64 + lane] = __float2half(vx * di);
            ho[(size_t)n * 64 + lane + 32] = __float2half(vy * di);
        }
    }
}

// ---------------- final MLP: one block per graph ----------------
__global__ __launch_bounds__(64) void k_mlp(const float* __restrict__ pW1,
                                            const float* __restrict__ pb1,
                                            const float* __restrict__ pW2,
                                            const float* __restrict__ pb2,
                                            float* __restrict__ out) {
    __shared__ float sp[HID];
    __shared__ float sh[HID];
    int g = blockIdx.x;
    int j = threadIdx.x;
    float c = (float)max(g_z.cnt[g], 1);
    sp[j] = g_z.pool[g * HID + j] / c;
    __syncthreads();
    float a = __ldg(&pb1[j]);
#pragma unroll 8
    for (int k = 0; k < HID; k++) a = fmaf(sp[k], __ldg(&pW1[k * HID + j]), a);
    sh[j] = a;
    __syncthreads();
    float b = __ldg(&pb2[j]);
#pragma unroll 8
    for (int k = 0; k < HID; k++) b = fmaf(sh[k], __ldg(&pW2[k * HID + j]), b);
    out[g * HID + j] = b;
}

// ---------------- launcher ----------------
extern "C" void kernel_launch(void* const* d_in, const int* in_sizes, int n_in,
                              void* d_out, int out_size) {
    const int* node = (const int*)d_in[0];
    const int* src = (const int*)d_in[1];
    const int* dst = (const int*)d_in[2];
    const int* batch = (const int*)d_in[3];
    const float* emb = (const float*)d_in[4];
    const float* W1 = (const float*)d_in[5];
    const float* b1 = (const float*)d_in[6];
    const float* W2 = (const float*)d_in[7];
    const float* b2 = (const float*)d_in[8];
    const float* W3 = (const float*)d_in[9];
    const float* b3 = (const float*)d_in[10];
    const float* ln1g = (const float*)d_in[11];
    const float* ln1b = (const float*)d_in[12];
    const float* ln2g = (const float*)d_in[13];
    const float* ln2b = (const float*)d_in[14];
    const float* pW1 = (const float*)d_in[15];
    const float* pb1 = (const float*)d_in[16];
    const float* pW2 = (const float*)d_in[17];
    const float* pb2 = (const float*)d_in[18];
    float* out = (float*)d_out;

    void* zptr = nullptr;
    cudaGetSymbolAddress(&zptr, g_z);
    void* xs1p = nullptr;
    cudaGetSymbolAddress(&xs1p, g_xs1);
    void* xs2p = nullptr;
    cudaGetSymbolAddress(&xs2p, g_xs2);
    __half2* xs1 = (__half2*)xs1p;
    __half2* xs2 = (__half2*)xs2p;

    cudaMemsetAsync(zptr, 0, sizeof(ZBlock));

    const int TB = 256;
    k_deg<<<(NE + TB - 1) / TB, TB>>>(dst);
    k_scan<<<(NN + TB - 1) / TB, TB>>>(node, emb);
    k_fill<<<(NE + TB - 1) / TB, TB>>>(src, dst);

    dim3 g16((NN * 16 + TB - 1) / TB);

    // layer 1 (16 lanes/node) -> xs1
    k_layer1<<<g16, TB>>>(W1, b1, ln1g, ln1b);
    // layer 2 fused gather+project (+LN) -> xs2, persistent blocks
    k_gcn<true, false><<<GCN_BLOCKS, TB>>>(xs1, W2, b2, ln2g, ln2b, nullptr, xs2);
    // layer 3 fused gather+project (+pool), persistent blocks
    k_gcn<false, true><<<GCN_BLOCKS, TB>>>(xs2, W3, b3, nullptr, nullptr, batch, nullptr);
    // MLP head: one block per graph
    k_mlp<<<NG, 64>>>(pW1, pb1, pW2, pb2, out);
}